// round 6
// baseline (speedup 1.0000x reference)
#include <cuda_runtime.h>

#define TPB 128
typedef unsigned long long ull;

// ---------------------------------------------------------------------------
// Precomputed (theta-dependent, batch-invariant), lane-interleaved layouts:
//  g_Wx : stages A,B,C (12 circuits). float2 at
//         [(((s*16+k)*8 + jj)*4 + t)*2 + half]  (jj=col/2, half=col%2)
//         => lane t reads ulonglong2 at ((s*16+k)*8+jj)*4 + t  (4 lanes = 64B)
//  g_Mx : stage D quad forms (4 circuits), float at
//         [((r*4 + j/4)*4 + t)*4 + j%4]
//  g_ME : stage E quad form, linear float[256]
// ---------------------------------------------------------------------------
__device__ __align__(16) float2 g_Wx[3072];   // 24 KB
__device__ __align__(16) float  g_Mx[1024];   // 4 KB
__device__ __align__(16) float  g_ME[256];    // 1 KB

// theta slice per circuit: A->theta[0], B->theta[3], C->theta[4], D->theta[1], E->theta[2][0]
__device__ __forceinline__ int circ_slice(int c) {
    if (c < 4)  return c;
    if (c < 8)  return 12 + (c - 4);
    if (c < 12) return 16 + (c - 8);
    if (c < 16) return 4 + (c - 12);
    return 8;
}

// One block per circuit (16 threads = 16 basis columns).
__global__ void build_WM(const float* __restrict__ theta) {
    const int c = blockIdx.x, col = threadIdx.x;
    const float* w = theta + circ_slice(c) * 48;

    float sr[16], si[16];
#pragma unroll
    for (int i = 0; i < 16; i++) { sr[i] = (i == col) ? 1.f : 0.f; si[i] = 0.f; }
#pragma unroll
    for (int l = 0; l < 4; l++) {
#pragma unroll
        for (int q = 0; q < 4; q++) {
            const float phi = w[(l * 4 + q) * 3 + 0];
            const float th  = w[(l * 4 + q) * 3 + 1];
            const float om  = w[(l * 4 + q) * 3 + 2];
            float ch, sh, ca, sa, cb, sb;
            __sincosf(0.5f * th, &sh, &ch);
            __sincosf(0.5f * (phi + om), &sa, &ca);
            __sincosf(0.5f * (phi - om), &sb, &cb);
            const float u00r =  ca * ch, u00i = -sa * ch;
            const float u01r = -cb * sh, u01i = -sb * sh;
            const float u10r =  cb * sh, u10i = -sb * sh;
            const float u11r =  ca * ch, u11i =  sa * ch;
            const int mask = 8 >> q;
#pragma unroll
            for (int k = 0; k < 16; k++) {
                if (k & mask) continue;
                const int k1 = k | mask;
                float ar = sr[k],  ai = si[k];
                float br = sr[k1], bi = si[k1];
                sr[k]  = u00r * ar - u00i * ai + u01r * br - u01i * bi;
                si[k]  = u00r * ai + u00i * ar + u01r * bi + u01i * br;
                sr[k1] = u10r * ar - u10i * ai + u11r * br - u11i * bi;
                si[k1] = u10r * ai + u10i * ar + u11r * bi + u11i * br;
            }
        }
        const int r = (l % 3) + 1;
#pragma unroll
        for (int q = 0; q < 4; q++) {
            const int cm = 8 >> q;
            const int tm = 8 >> ((q + r) & 3);
#pragma unroll
            for (int k = 0; k < 16; k++) {
                if ((k & cm) && !(k & tm)) {
                    const int k1 = k | tm;
                    float tr = sr[k], ti = si[k];
                    sr[k] = sr[k1]; si[k] = si[k1];
                    sr[k1] = tr;    si[k1] = ti;
                }
            }
        }
    }

    if (c < 12) {
        const int s = c >> 2, t = c & 3;
#pragma unroll
        for (int k = 0; k < 16; k++)
            g_Wx[(((s * 16 + k) * 8 + (col >> 1)) * 4 + t) * 2 + (col & 1)] =
                make_float2(sr[k], si[k]);
    } else {
        __shared__ float2 sWt[256];
#pragma unroll
        for (int k = 0; k < 16; k++) sWt[k * 16 + col] = make_float2(sr[k], si[k]);
        __syncthreads();
        const int r = col;
        float m[16];
#pragma unroll
        for (int j = 0; j < 16; j++) m[j] = 0.f;
#pragma unroll
        for (int k = 0; k < 16; k++) {
            const float2 wr = sWt[k * 16 + r];
#pragma unroll
            for (int j = 0; j < 16; j++) {
                const float2 wj = sWt[k * 16 + j];
                const float tt = wr.x * wj.x + wr.y * wj.y;
                m[j] = (k & 8) ? (m[j] - tt) : (m[j] + tt);
            }
        }
        if (c < 16) {
            const int t = c - 12;
#pragma unroll
            for (int j = 0; j < 16; j++)
                g_Mx[((r * 4 + (j >> 2)) * 4 + t) * 4 + (j & 3)] = m[j];
        } else {
#pragma unroll
            for (int j = 0; j < 16; j++) g_ME[r * 16 + j] = m[j];
        }
    }
}

// ---------------------------------------------------------------------------
// f32x2 packed helpers
// ---------------------------------------------------------------------------
__device__ __forceinline__ ull pk2(float lo, float hi) {
    ull r; asm("mov.b64 %0, {%1, %2};" : "=l"(r) : "f"(lo), "f"(hi)); return r;
}
__device__ __forceinline__ void unpk2(ull v, float& lo, float& hi) {
    asm("mov.b64 {%0, %1}, %2;" : "=f"(lo), "=f"(hi) : "l"(v));
}
__device__ __forceinline__ ull ffma2(ull a, ull b, ull c) {
    ull d; asm("fma.rn.f32x2 %0, %1, %2, %3;" : "=l"(d) : "l"(a), "l"(b), "l"(c)); return d;
}
__device__ __forceinline__ ull fmul2(ull a, ull b) {
    ull d; asm("mul.rn.f32x2 %0, %1, %2;" : "=l"(d) : "l"(a), "l"(b)); return d;
}
__device__ __forceinline__ ull fadd2(ull a, ull b) {
    ull d; asm("add.rn.f32x2 %0, %1, %2;" : "=l"(d) : "l"(a), "l"(b)); return d;
}

__device__ __forceinline__ void emb2(float a0, float a1, float* u) {
    float s0, c0, s1, c1;
    __sincosf(0.5f * a0, &s0, &c0);
    __sincosf(0.5f * a1, &s1, &c1);
    u[0] = c0 * c1; u[1] = c0 * s1; u[2] = s0 * c1; u[3] = s0 * s1;
}

// Full circuit, 4 expvals. pW = lane-interleaved base (ulonglong2, stride 4 per jj).
__device__ __forceinline__ void run4_i(const ulonglong2* __restrict__ pW,
                                       const float* a, float* o) {
    float u[4], v[4];
    emb2(a[0], a[1], u); emb2(a[2], a[3], v);
    ull pp[16];
#pragma unroll
    for (int i = 0; i < 4; i++)
#pragma unroll
        for (int j = 0; j < 4; j++) { const float t = u[i] * v[j]; pp[i * 4 + j] = pk2(t, t); }
    float e0 = 0.f, e1 = 0.f, e2 = 0.f, e3 = 0.f;
#pragma unroll
    for (int k = 0; k < 16; k++) {
        const ulonglong2* row = pW + k * 32;                  // 8 jj * stride 4
        const ulonglong2 w0 = row[0], w1 = row[4];
        ull ac0 = fmul2(w0.x, pp[0]), ac2 = fmul2(w0.y, pp[1]);
        ull ac1 = fmul2(w1.x, pp[2]), ac3 = fmul2(w1.y, pp[3]);
#pragma unroll
        for (int jj = 2; jj < 8; jj += 2) {
            const ulonglong2 wA = row[jj * 4], wB = row[jj * 4 + 4];
            ac0 = ffma2(wA.x, pp[2 * jj],     ac0);
            ac2 = ffma2(wA.y, pp[2 * jj + 1], ac2);
            ac1 = ffma2(wB.x, pp[2 * jj + 2], ac1);
            ac3 = ffma2(wB.y, pp[2 * jj + 3], ac3);
        }
        const ull s = fadd2(fadd2(ac0, ac1), fadd2(ac2, ac3));
        float yr, yi; unpk2(s, yr, yi);
        const float p = fmaf(yr, yr, yi * yi);
        e0 = (k & 8) ? (e0 - p) : (e0 + p);
        e1 = (k & 4) ? (e1 - p) : (e1 + p);
        e2 = (k & 2) ? (e2 - p) : (e2 + p);
        e3 = (k & 1) ? (e3 - p) : (e3 + p);
    }
    o[0] = e0; o[1] = e1; o[2] = e2; o[3] = e3;
}

// Single expval, e = psi^T M psi. Stride = ulonglong2 step between the 4 row
// chunks (4 for lane-interleaved stage D, 1 for broadcast stage E).
template <int STRIDE>
__device__ __forceinline__ float run1_s(const ulonglong2* __restrict__ pM,
                                        const float* a) {
    float u[4], v[4];
    emb2(a[0], a[1], u); emb2(a[2], a[3], v);
    float psi[16];
#pragma unroll
    for (int i = 0; i < 4; i++)
#pragma unroll
        for (int j = 0; j < 4; j++) psi[i * 4 + j] = u[i] * v[j];
    ull pj[8];
#pragma unroll
    for (int j = 0; j < 8; j++) pj[j] = pk2(psi[2 * j], psi[2 * j + 1]);
    float e = 0.f;
#pragma unroll
    for (int k = 0; k < 16; k++) {
        const ulonglong2* row = pM + k * 4 * STRIDE;
        const ulonglong2 m0 = row[0], m1 = row[STRIDE], m2 = row[2 * STRIDE], m3 = row[3 * STRIDE];
        ull a0c = fmul2(m0.x, pj[0]);
        ull a1c = fmul2(m0.y, pj[1]);
        a0c = ffma2(m1.x, pj[2], a0c);
        a1c = ffma2(m1.y, pj[3], a1c);
        a0c = ffma2(m2.x, pj[4], a0c);
        a1c = ffma2(m2.y, pj[5], a1c);
        a0c = ffma2(m3.x, pj[6], a0c);
        a1c = ffma2(m3.y, pj[7], a1c);
        const ull s = fadd2(a0c, a1c);
        float lo, hi; unpk2(s, lo, hi);
        e = fmaf(psi[k], lo + hi, e);
    }
    return e;
}

// ---------------------------------------------------------------------------
// Main kernel: 4 threads per batch element, conflict-free interleaved smem.
// ---------------------------------------------------------------------------
__global__ __launch_bounds__(TPB, 7)
void vqc_main4(const float* __restrict__ x, float* __restrict__ out, int B) {
    __shared__ __align__(16) ulonglong2 sWx[1536];        // 24 KB
    __shared__ __align__(16) ulonglong2 sMx[256];         // 4 KB
    __shared__ __align__(16) float      sME[256];         // 1 KB
    __shared__ float xch[TPB / 4][20];                    // 2.5 KB, padded

    const int tid = threadIdx.x;
    {
        const float4* s1 = (const float4*)g_Wx;
        float4* d1 = (float4*)sWx;
        for (int i = tid; i < 1536; i += TPB) d1[i] = s1[i];
        const float4* s2 = (const float4*)g_Mx;
        float4* d2 = (float4*)sMx;
        for (int i = tid; i < 256; i += TPB) d2[i] = s2[i];
        const float4* s3 = (const float4*)g_ME;
        float4* d3 = (float4*)sME;
        for (int i = tid; i < 64; i += TPB) d3[i] = s3[i];
    }
    __syncthreads();

    const int g = tid >> 2;                      // quad within block
    const int t = tid & 3;                       // lane role 0..3
    int grp = blockIdx.x * (TPB / 4) + g;        // batch element
    const bool live = grp < B;
    if (!live) grp = B - 1;

    // Stage-A angles: H = [0, x0..x12, 0, 0]; lane t uses H[4t..4t+3]
    float a[4];
    const float* xb = x + (long)grp * 13;
#pragma unroll
    for (int i = 0; i < 4; i++) {
        const int j = 4 * t + i;
        a[i] = (j >= 1 && j < 14) ? xb[j - 1] : 0.f;
    }

    float o[4];
    // Stage A: lane t = circuit t
    run4_i(sWx + (0 * 16) * 32 + t, a, o);
    __syncwarp();
    *(float4*)&xch[g][t * 4] = make_float4(o[0], o[1], o[2], o[3]);
    __syncwarp();
#pragma unroll
    for (int i = 0; i < 4; i++) a[i] = xch[g][i * 4 + t];
    // Stage B
    run4_i(sWx + (1 * 16) * 32 + t, a, o);
    __syncwarp();
    *(float4*)&xch[g][t * 4] = make_float4(o[0], o[1], o[2], o[3]);
    __syncwarp();
#pragma unroll
    for (int i = 0; i < 4; i++) a[i] = xch[g][i * 4 + t];
    // Stage C
    run4_i(sWx + (2 * 16) * 32 + t, a, o);
    __syncwarp();
    *(float4*)&xch[g][t * 4] = make_float4(o[0], o[1], o[2], o[3]);
    __syncwarp();
#pragma unroll
    for (int i = 0; i < 4; i++) a[i] = xch[g][i * 4 + t];
    // Stage D: one quad form per lane
    const float h4 = run1_s<4>(sMx + t, a);
    __syncwarp();
    xch[g][t] = h4;
    __syncwarp();
#pragma unroll
    for (int i = 0; i < 4; i++) a[i] = xch[g][i];
    // Stage E: redundant on all lanes, lane 0 writes
    const float e = run1_s<1>((const ulonglong2*)sME, a);
    if (t == 0 && live)
        out[grp] = e * (float)(3.141592653589793 - 1.1920928955078125e-7);
}

extern "C" void kernel_launch(void* const* d_in, const int* in_sizes, int n_in,
                              void* d_out, int out_size) {
    const float* x     = (const float*)d_in[0];
    const float* theta = (const float*)d_in[1];
    if (n_in >= 2 && in_sizes[0] < in_sizes[1]) {
        x     = (const float*)d_in[1];
        theta = (const float*)d_in[0];
    }
    float* out = (float*)d_out;
    const int B = out_size;

    build_WM<<<17, 16>>>(theta);
    const int gpb = TPB / 4;                       // elements per block
    vqc_main4<<<(B + gpb - 1) / gpb, TPB>>>(x, out, B);
}

// round 7
// speedup vs baseline: 1.4112x; 1.4112x over previous
#include <cuda_runtime.h>

#define TPB 128
typedef unsigned long long ull;

// Precomputed (theta-dependent, batch-invariant), row-major broadcast layout:
__device__ __align__(16) float2 g_W12[12 * 256];   // unitaries, circuits 0..11 (stages A,B,C)
__device__ __align__(16) float  g_M[5 * 256];      // quadratic forms, circuits 12..16 (D,E)

// theta slice per circuit: A->theta[0], B->theta[3], C->theta[4], D->theta[1], E->theta[2][0]
__device__ __forceinline__ int circ_slice(int c) {
    if (c < 4)  return c;
    if (c < 8)  return 12 + (c - 4);
    if (c < 12) return 16 + (c - 8);
    if (c < 16) return 4 + (c - 12);
    return 8;
}

// One block per circuit (16 threads = 16 basis columns).
__global__ void build_WM(const float* __restrict__ theta) {
    const int c = blockIdx.x, col = threadIdx.x;
    const float* w = theta + circ_slice(c) * 48;

    float sr[16], si[16];
#pragma unroll
    for (int i = 0; i < 16; i++) { sr[i] = (i == col) ? 1.f : 0.f; si[i] = 0.f; }
#pragma unroll
    for (int l = 0; l < 4; l++) {
#pragma unroll
        for (int q = 0; q < 4; q++) {
            const float phi = w[(l * 4 + q) * 3 + 0];
            const float th  = w[(l * 4 + q) * 3 + 1];
            const float om  = w[(l * 4 + q) * 3 + 2];
            float ch, sh, ca, sa, cb, sb;
            __sincosf(0.5f * th, &sh, &ch);
            __sincosf(0.5f * (phi + om), &sa, &ca);
            __sincosf(0.5f * (phi - om), &sb, &cb);
            const float u00r =  ca * ch, u00i = -sa * ch;
            const float u01r = -cb * sh, u01i = -sb * sh;
            const float u10r =  cb * sh, u10i = -sb * sh;
            const float u11r =  ca * ch, u11i =  sa * ch;
            const int mask = 8 >> q;
#pragma unroll
            for (int k = 0; k < 16; k++) {
                if (k & mask) continue;
                const int k1 = k | mask;
                float ar = sr[k],  ai = si[k];
                float br = sr[k1], bi = si[k1];
                sr[k]  = u00r * ar - u00i * ai + u01r * br - u01i * bi;
                si[k]  = u00r * ai + u00i * ar + u01r * bi + u01i * br;
                sr[k1] = u10r * ar - u10i * ai + u11r * br - u11i * bi;
                si[k1] = u10r * ai + u10i * ar + u11r * bi + u11i * br;
            }
        }
        const int r = (l % 3) + 1;
#pragma unroll
        for (int q = 0; q < 4; q++) {
            const int cm = 8 >> q;
            const int tm = 8 >> ((q + r) & 3);
#pragma unroll
            for (int k = 0; k < 16; k++) {
                if ((k & cm) && !(k & tm)) {
                    const int k1 = k | tm;
                    float tr = sr[k], ti = si[k];
                    sr[k] = sr[k1]; si[k] = si[k1];
                    sr[k1] = tr;    si[k1] = ti;
                }
            }
        }
    }

    if (c < 12) {
#pragma unroll
        for (int k = 0; k < 16; k++)
            g_W12[c * 256 + k * 16 + col] = make_float2(sr[k], si[k]);
    } else {
        __shared__ float2 sWt[256];
#pragma unroll
        for (int k = 0; k < 16; k++) sWt[k * 16 + col] = make_float2(sr[k], si[k]);
        __syncthreads();
        const int r = col;
        float m[16];
#pragma unroll
        for (int j = 0; j < 16; j++) m[j] = 0.f;
#pragma unroll
        for (int k = 0; k < 16; k++) {
            const float2 wr = sWt[k * 16 + r];
#pragma unroll
            for (int j = 0; j < 16; j++) {
                const float2 wj = sWt[k * 16 + j];
                const float tt = wr.x * wj.x + wr.y * wj.y;
                m[j] = (k & 8) ? (m[j] - tt) : (m[j] + tt);
            }
        }
#pragma unroll
        for (int j = 0; j < 16; j++) g_M[(c - 12) * 256 + r * 16 + j] = m[j];
    }
}

// ---------------------------------------------------------------------------
// f32x2 packed helpers
// ---------------------------------------------------------------------------
__device__ __forceinline__ ull pk2(float lo, float hi) {
    ull r; asm("mov.b64 %0, {%1, %2};" : "=l"(r) : "f"(lo), "f"(hi)); return r;
}
__device__ __forceinline__ void unpk2(ull v, float& lo, float& hi) {
    asm("mov.b64 {%0, %1}, %2;" : "=f"(lo), "=f"(hi) : "l"(v));
}
__device__ __forceinline__ ull ffma2(ull a, ull b, ull c) {
    ull d; asm("fma.rn.f32x2 %0, %1, %2, %3;" : "=l"(d) : "l"(a), "l"(b), "l"(c)); return d;
}
__device__ __forceinline__ ull fmul2(ull a, ull b) {
    ull d; asm("mul.rn.f32x2 %0, %1, %2;" : "=l"(d) : "l"(a), "l"(b)); return d;
}
__device__ __forceinline__ ull fadd2(ull a, ull b) {
    ull d; asm("add.rn.f32x2 %0, %1, %2;" : "=l"(d) : "l"(a), "l"(b)); return d;
}

__device__ __forceinline__ void emb2(float a0, float a1, float* u) {
    float s0, c0, s1, c1;
    __sincosf(0.5f * a0, &s0, &c0);
    __sincosf(0.5f * a1, &s1, &c1);
    u[0] = c0 * c1; u[1] = c0 * s1; u[2] = s0 * c1; u[3] = s0 * s1;
}

// Full circuit, 4 expvals. W rows packed as f32x2 complex, broadcast reads.
__device__ __forceinline__ void run4(const ull* __restrict__ W, const float* a, float* o) {
    float u[4], v[4];
    emb2(a[0], a[1], u); emb2(a[2], a[3], v);
    ull pp[16];
#pragma unroll
    for (int i = 0; i < 4; i++)
#pragma unroll
        for (int j = 0; j < 4; j++) { const float t = u[i] * v[j]; pp[i * 4 + j] = pk2(t, t); }
    float e0 = 0.f, e1 = 0.f, e2 = 0.f, e3 = 0.f;
#pragma unroll 4
    for (int k = 0; k < 16; k++) {
        const ulonglong2* row = (const ulonglong2*)(W + k * 16);
        const ulonglong2 w0 = row[0], w1 = row[1];
        ull ac0 = fmul2(w0.x, pp[0]), ac2 = fmul2(w0.y, pp[1]);
        ull ac1 = fmul2(w1.x, pp[2]), ac3 = fmul2(w1.y, pp[3]);
#pragma unroll
        for (int jj = 2; jj < 8; jj += 2) {
            const ulonglong2 wA = row[jj], wB = row[jj + 1];
            ac0 = ffma2(wA.x, pp[2 * jj],     ac0);
            ac2 = ffma2(wA.y, pp[2 * jj + 1], ac2);
            ac1 = ffma2(wB.x, pp[2 * jj + 2], ac1);
            ac3 = ffma2(wB.y, pp[2 * jj + 3], ac3);
        }
        const ull s = fadd2(fadd2(ac0, ac1), fadd2(ac2, ac3));
        float yr, yi; unpk2(s, yr, yi);
        const float p = fmaf(yr, yr, yi * yi);
        e0 = (k & 8) ? (e0 - p) : (e0 + p);
        e1 = (k & 4) ? (e1 - p) : (e1 + p);
        e2 = (k & 2) ? (e2 - p) : (e2 + p);
        e3 = (k & 1) ? (e3 - p) : (e3 + p);
    }
    o[0] = e0; o[1] = e1; o[2] = e2; o[3] = e3;
}

// Single expval via real quadratic form e = psi^T M psi (broadcast reads).
__device__ __forceinline__ float run1(const float* __restrict__ M, const float* a) {
    float u[4], v[4];
    emb2(a[0], a[1], u); emb2(a[2], a[3], v);
    float psi[16];
#pragma unroll
    for (int i = 0; i < 4; i++)
#pragma unroll
        for (int j = 0; j < 4; j++) psi[i * 4 + j] = u[i] * v[j];
    ull pj[8];
#pragma unroll
    for (int j = 0; j < 8; j++) pj[j] = pk2(psi[2 * j], psi[2 * j + 1]);
    float e = 0.f;
#pragma unroll
    for (int k = 0; k < 16; k++) {
        const ulonglong2* row = (const ulonglong2*)(M + k * 16);
        const ulonglong2 m0 = row[0], m1 = row[1], m2 = row[2], m3 = row[3];
        ull a0c = fmul2(m0.x, pj[0]);
        ull a1c = fmul2(m0.y, pj[1]);
        a0c = ffma2(m1.x, pj[2], a0c);
        a1c = ffma2(m1.y, pj[3], a1c);
        a0c = ffma2(m2.x, pj[4], a0c);
        a1c = ffma2(m2.y, pj[5], a1c);
        a0c = ffma2(m3.x, pj[6], a0c);
        a1c = ffma2(m3.y, pj[7], a1c);
        const ull s = fadd2(a0c, a1c);
        float lo, hi; unpk2(s, lo, hi);
        e = fmaf(psi[k], lo + hi, e);
    }
    return e;
}

// ---------------------------------------------------------------------------
// Main kernel: block = 32-element tile, warp w = circuit w of each stage,
// lane = element. All W/M reads are full-warp broadcasts.
// ---------------------------------------------------------------------------
__global__ __launch_bounds__(TPB, 7)
void vqc_warp(const float* __restrict__ x, float* __restrict__ out, int B) {
    __shared__ __align__(16) ull   sW[12 * 256];   // 24 KB
    __shared__ __align__(16) float sM[5 * 256];    // 5 KB
    __shared__ float sH[32][17];                   // 2.1 KB, stride-17 pad

    const int tid = threadIdx.x;
    {
        const float4* s1 = (const float4*)g_W12;
        float4* d1 = (float4*)sW;
        for (int i = tid; i < 12 * 128; i += TPB) d1[i] = s1[i];
        const float4* s2 = (const float4*)g_M;
        float4* d2 = (float4*)sM;
        for (int i = tid; i < 5 * 64; i += TPB) d2[i] = s2[i];
    }

    const int e0 = blockIdx.x * 32;                 // tile base element
    // Coalesced x tile load: 32*13 contiguous floats -> sH[e][0..12]
    for (int i = tid; i < 32 * 13; i += TPB) {
        const long gi = (long)e0 * 13 + i;
        if (gi < (long)B * 13) {
            const int e = i / 13, j = i - 13 * e;
            sH[e][j] = x[gi];
        }
    }
    __syncthreads();

    const int w = tid >> 5;   // warp = circuit index within stage
    const int e = tid & 31;   // lane  = element within tile
    float a[4], o[4];

    // Stage A angles: H = [0, x0..x12, 0, 0]; circuit w uses H[4w..4w+3]
#pragma unroll
    for (int i = 0; i < 4; i++) {
        const int j = 4 * w + i;
        a[i] = (j >= 1 && j <= 13) ? sH[e][j - 1] : 0.f;
    }
    __syncthreads();

    // Stage A
    run4(sW + w * 256, a, o);
#pragma unroll
    for (int i = 0; i < 4; i++) sH[e][4 * w + i] = o[i];
    __syncthreads();
#pragma unroll
    for (int i = 0; i < 4; i++) a[i] = sH[e][4 * i + w];    // transposed wiring
    __syncthreads();

    // Stage B
    run4(sW + (4 + w) * 256, a, o);
#pragma unroll
    for (int i = 0; i < 4; i++) sH[e][4 * w + i] = o[i];
    __syncthreads();
#pragma unroll
    for (int i = 0; i < 4; i++) a[i] = sH[e][4 * i + w];
    __syncthreads();

    // Stage C
    run4(sW + (8 + w) * 256, a, o);
#pragma unroll
    for (int i = 0; i < 4; i++) sH[e][4 * w + i] = o[i];
    __syncthreads();
#pragma unroll
    for (int i = 0; i < 4; i++) a[i] = sH[e][4 * i + w];
    __syncthreads();

    // Stage D: quadratic form w
    const float h4 = run1(sM + w * 256, a);
    sH[e][w] = h4;
    __syncthreads();

    // Stage E: warp 0 only (warp-uniform branch; no further barriers)
    if (w != 0) return;
#pragma unroll
    for (int i = 0; i < 4; i++) a[i] = sH[e][i];
    const float r = run1(sM + 4 * 256, a);
    if (e0 + e < B)
        out[e0 + e] = r * (float)(3.141592653589793 - 1.1920928955078125e-7);
}

extern "C" void kernel_launch(void* const* d_in, const int* in_sizes, int n_in,
                              void* d_out, int out_size) {
    const float* x     = (const float*)d_in[0];
    const float* theta = (const float*)d_in[1];
    if (n_in >= 2 && in_sizes[0] < in_sizes[1]) {
        x     = (const float*)d_in[1];
        theta = (const float*)d_in[0];
    }
    float* out = (float*)d_out;
    const int B = out_size;

    build_WM<<<17, 16>>>(theta);
    vqc_warp<<<(B + 31) / 32, TPB>>>(x, out, B);
}